// round 3
// baseline (speedup 1.0000x reference)
#include <cuda_runtime.h>

// out[b, q] = cos(x[b, q] + w[q]),  x: [4194304, 24] f32, w: [24] f32.
// As float4s: n4 = n/4, weight-vector index of float4 i is (i % 6).
// THREADS=192 and 192 % 6 == 0  ==>  (base + k*192) % 6 == tid % 6 for all k
// (block offset THREADS*U*blockIdx is divisible by 6 too), so each thread
// uses ONE weight float4, loaded once. U=8 loads batched -> MLP = 8.

#define THREADS 192
#define U 8

__global__ __launch_bounds__(THREADS)
void qfl_cos_kernel(const float4* __restrict__ x,
                    const float4* __restrict__ w4,
                    float4* __restrict__ out,
                    int n4) {
    int tid  = threadIdx.x;
    int base = blockIdx.x * (THREADS * U) + tid;

    int m = tid % 6;                 // loop-invariant weight index
    float4 W = __ldg(&w4[m]);        // one 16B load, L1/const-hit broadcast

    if (base + (U - 1) * THREADS < n4) {
        float4 v[U];
#pragma unroll
        for (int k = 0; k < U; k++)
            v[k] = __ldcs(&x[base + k * THREADS]);

#pragma unroll
        for (int k = 0; k < U; k++) {
            float4 r;
            r.x = cosf(v[k].x + W.x);
            r.y = cosf(v[k].y + W.y);
            r.z = cosf(v[k].z + W.z);
            r.w = cosf(v[k].w + W.w);
            __stcs(&out[base + k * THREADS], r);
        }
    } else {
        // Tail (unused for the bench shape: 25165824 % 1536 == 0)
#pragma unroll
        for (int k = 0; k < U; k++) {
            int i = base + k * THREADS;
            if (i < n4) {
                float4 v = __ldcs(&x[i]);
                float4 r;
                r.x = cosf(v.x + W.x);
                r.y = cosf(v.y + W.y);
                r.z = cosf(v.z + W.z);
                r.w = cosf(v.w + W.w);
                __stcs(&out[i], r);
            }
        }
    }
}

extern "C" void kernel_launch(void* const* d_in, const int* in_sizes, int n_in,
                              void* d_out, int out_size) {
    const float* x = (const float*)d_in[0];
    const float* w = (const float*)d_in[1];
    float* out = (float*)d_out;

    int n  = in_sizes[0];   // 100663296
    int n4 = n >> 2;        // 25165824 = 16384 * 1536 (exact)

    int per_block = THREADS * U;     // 1536
    int blocks = (n4 + per_block - 1) / per_block;
    qfl_cos_kernel<<<blocks, THREADS>>>((const float4*)x, (const float4*)w,
                                        (float4*)out, n4);
}

// round 4
// speedup vs baseline: 1.0505x; 1.0505x over previous
#include <cuda_runtime.h>

// out[b, q] = cos(x[b, q] + w[q]),  x: [4194304, 24] f32, w: [24] f32.
// As float4s: weight-vector index of float4 i is (i % 6).
// THREADS=384 (divisible by 6) with block-stride =>
//   (blockIdx*1536 + k*384 + tid) % 6 == tid % 6  for all k,
// so each thread loads ONE weight float4 once. U=4 keeps regs ~32 so
// occupancy stays high (the R3 U=8 variant hit 54 regs / 55% occ and lost).

#define THREADS 384
#define U 4

__global__ __launch_bounds__(THREADS, 5)
void qfl_cos_kernel(const float4* __restrict__ x,
                    const float4* __restrict__ w4,
                    float4* __restrict__ out,
                    int n4) {
    int tid  = threadIdx.x;
    int base = blockIdx.x * (THREADS * U) + tid;

    float4 W = __ldg(&w4[tid % 6]);   // loop-invariant, one 16B broadcast load

    if (base + (U - 1) * THREADS < n4) {
        float4 v[U];
#pragma unroll
        for (int k = 0; k < U; k++)
            v[k] = __ldcs(&x[base + k * THREADS]);

#pragma unroll
        for (int k = 0; k < U; k++) {
            float4 r;
            r.x = cosf(v[k].x + W.x);
            r.y = cosf(v[k].y + W.y);
            r.z = cosf(v[k].z + W.z);
            r.w = cosf(v[k].w + W.w);
            __stcs(&out[base + k * THREADS], r);
        }
    } else {
        // Tail (unused for the bench shape: 25165824 % 1536 == 0)
#pragma unroll
        for (int k = 0; k < U; k++) {
            int i = base + k * THREADS;
            if (i < n4) {
                float4 v = __ldcs(&x[i]);
                float4 r;
                r.x = cosf(v.x + W.x);
                r.y = cosf(v.y + W.y);
                r.z = cosf(v.z + W.z);
                r.w = cosf(v.w + W.w);
                __stcs(&out[i], r);
            }
        }
    }
}

extern "C" void kernel_launch(void* const* d_in, const int* in_sizes, int n_in,
                              void* d_out, int out_size) {
    const float* x = (const float*)d_in[0];
    const float* w = (const float*)d_in[1];
    float* out = (float*)d_out;

    int n  = in_sizes[0];   // 100663296
    int n4 = n >> 2;        // 25165824 = 16384 * 1536 (exact)

    int per_block = THREADS * U;     // 1536
    int blocks = (n4 + per_block - 1) / per_block;
    qfl_cos_kernel<<<blocks, THREADS>>>((const float4*)x, (const float4*)w,
                                        (float4*)out, n4);
}

// round 5
// speedup vs baseline: 1.0649x; 1.0137x over previous
#include <cuda_runtime.h>

// out[b, q] = cos(x[b, q] + w[q]),  x: [4194304, 24] f32, w: [24] f32.
// Weight-vector index of float4 i is (i % 6); THREADS=384 divisible by 6
// makes it the loop-invariant (tid % 6). __cosf -> MUFU.COS: ~1-2 instrs
// per element vs ~15 for precise cosf; abs err ~1e-7 for |arg|<~8, far
// inside the 1e-3 rel_err gate. Kernel is HBM-bound; compute fully hidden.

#define THREADS 384
#define U 4

__global__ __launch_bounds__(THREADS, 5)
void qfl_cos_kernel(const float4* __restrict__ x,
                    const float4* __restrict__ w4,
                    float4* __restrict__ out,
                    int n4) {
    int tid  = threadIdx.x;
    int base = blockIdx.x * (THREADS * U) + tid;

    float4 W = __ldg(&w4[tid % 6]);   // loop-invariant, one 16B broadcast load

    if (base + (U - 1) * THREADS < n4) {
        float4 v[U];
#pragma unroll
        for (int k = 0; k < U; k++)
            v[k] = __ldcs(&x[base + k * THREADS]);

#pragma unroll
        for (int k = 0; k < U; k++) {
            float4 r;
            r.x = __cosf(v[k].x + W.x);
            r.y = __cosf(v[k].y + W.y);
            r.z = __cosf(v[k].z + W.z);
            r.w = __cosf(v[k].w + W.w);
            __stcs(&out[base + k * THREADS], r);
        }
    } else {
        // Tail (unused for the bench shape: 25165824 % 1536 == 0)
#pragma unroll
        for (int k = 0; k < U; k++) {
            int i = base + k * THREADS;
            if (i < n4) {
                float4 v = __ldcs(&x[i]);
                float4 r;
                r.x = __cosf(v.x + W.x);
                r.y = __cosf(v.y + W.y);
                r.z = __cosf(v.z + W.z);
                r.w = __cosf(v.w + W.w);
                __stcs(&out[i], r);
            }
        }
    }
}

extern "C" void kernel_launch(void* const* d_in, const int* in_sizes, int n_in,
                              void* d_out, int out_size) {
    const float* x = (const float*)d_in[0];
    const float* w = (const float*)d_in[1];
    float* out = (float*)d_out;

    int n  = in_sizes[0];   // 100663296
    int n4 = n >> 2;        // 25165824 = 16384 * 1536 (exact)

    int per_block = THREADS * U;     // 1536
    int blocks = (n4 + per_block - 1) / per_block;
    qfl_cos_kernel<<<blocks, THREADS>>>((const float4*)x, (const float4*)w,
                                        (float4*)out, n4);
}